// round 5
// baseline (speedup 1.0000x reference)
#include <cuda_runtime.h>
#include <math.h>

#define D_IN   256
#define D_EMB  512
#define K_CB   2048
#define T_MAX  65536

#define TOK_TILE 64
#define CB_TILE  128
#define KK_CHUNK 64
#define FPAD 68
#define APAD 132
#define K2_SMEM ((D_IN * FPAD + KK_CHUNK * APAD) * 4 + 64 * 4 + 64 * 16 * 4)
#define MARGIN 1.4e-4f
#define NB_EXACT 2048

typedef unsigned long long u64;

// ---------------- scratch (device globals; no allocations allowed) -----------
__device__ __align__(16) float g_AT[D_IN * K_CB];   // A transposed [i][k]
__device__ __align__(16) float g_Q[K_CB * D_IN];    // fused output codebook [k][j]
__device__ float g_c[K_CB];
__device__ float g_se[K_CB];                        // fp32 sum of e^2 per codeword
__device__ float g_b1eff[D_EMB];
__device__ int g_idx[T_MAX];
__device__ unsigned int g_hist[K_CB];
__device__ double g_partial[8192];
__device__ int g_ccount[T_MAX];
__device__ unsigned short g_cand[T_MAX][16];
__device__ int g_needy[T_MAX];
__device__ int g_nneedy;

// ---------------- K0: b1eff, zero hist/counters ------------------------------
__global__ void k0_init(const float* __restrict__ W1, const float* __restrict__ b1,
                        const float* __restrict__ beta1) {
    int t = blockIdx.x * blockDim.x + threadIdx.x;
    if (t < D_EMB) {
        float s = b1[t];
        for (int i = 0; i < D_IN; i++) s = fmaf(beta1[i], W1[t * D_IN + i], s);
        g_b1eff[t] = s;
    }
    if (t < K_CB) g_hist[t] = 0u;
    if (t == 0) g_nneedy = 0;
}

// ---------------- K1: precompute AT and Q (approx path, tolerance-fine) ------
#define K1_ROWS 16
#define EPAD 20
__global__ __launch_bounds__(256) void k1_precompute(
    const float* __restrict__ emb, const float* __restrict__ W1,
    const float* __restrict__ W2, const float* __restrict__ g1v,
    const float* __restrict__ g2v, const float* __restrict__ beta2,
    const float* __restrict__ b2) {
    __shared__ float sE[D_EMB * EPAD];
    __shared__ float sG2[D_EMB];
    __shared__ float sB2[D_EMB];
    const int t = threadIdx.x;
    const int k0 = blockIdx.x * K1_ROWS;
    const float bn_s = rsqrtf(1.0f + 1e-5f);

    {
        int r = t & 15, ov = t >> 4;
        for (int pass = 0; pass < 8; pass++) {
            int o4 = ov + pass * 16;
            float4 v = *(const float4*)&emb[(size_t)(k0 + r) * D_EMB + o4 * 4];
            sE[(o4 * 4 + 0) * EPAD + r] = v.x;
            sE[(o4 * 4 + 1) * EPAD + r] = v.y;
            sE[(o4 * 4 + 2) * EPAD + r] = v.z;
            sE[(o4 * 4 + 3) * EPAD + r] = v.w;
        }
    }
    for (int i = t; i < D_EMB; i += 256) {
        sG2[i] = g2v[i] * bn_s;
        sB2[i] = beta2[i];
    }
    __syncthreads();

    const int j = t;
    float accA[16], accQ[16];
    float qc = 0.f;
#pragma unroll
    for (int r = 0; r < 16; r++) { accA[r] = 0.f; accQ[r] = 0.f; }

#pragma unroll 2
    for (int o = 0; o < D_EMB; o++) {
        float w1 = W1[o * D_IN + j];
        float w2 = W2[j * D_EMB + o];
        float gw = sG2[o] * w2;
        qc = fmaf(sB2[o], w2, qc);
        const float* e = &sE[o * EPAD];
        float4 e0 = *(const float4*)(e + 0);
        float4 e1 = *(const float4*)(e + 4);
        float4 e2 = *(const float4*)(e + 8);
        float4 e3 = *(const float4*)(e + 12);
        float ev[16] = {e0.x,e0.y,e0.z,e0.w, e1.x,e1.y,e1.z,e1.w,
                        e2.x,e2.y,e2.z,e2.w, e3.x,e3.y,e3.z,e3.w};
#pragma unroll
        for (int r = 0; r < 16; r++) {
            accA[r] = fmaf(ev[r], w1, accA[r]);
            accQ[r] = fmaf(ev[r], gw, accQ[r]);
        }
    }
    float g1j = g1v[j] * bn_s;
    float b2j = b2[j];
#pragma unroll
    for (int r4 = 0; r4 < 4; r4++) {
        float4 va;
        va.x = g1j * accA[r4*4+0]; va.y = g1j * accA[r4*4+1];
        va.z = g1j * accA[r4*4+2]; va.w = g1j * accA[r4*4+3];
        *(float4*)&g_AT[(size_t)j * K_CB + k0 + r4 * 4] = va;
    }
#pragma unroll
    for (int r = 0; r < 16; r++)
        g_Q[(size_t)(k0 + r) * D_IN + j] = accQ[r] + qc + b2j;
}

// ---------------- K1b: c[k] (approx) and se[k] (fp32 sum of squares) ---------
__global__ __launch_bounds__(256) void k1b_c(const float* __restrict__ emb) {
    int w = blockIdx.x * 8 + (threadIdx.x >> 5);
    int lane = threadIdx.x & 31;
    if (w >= K_CB) return;
    float s = 0.f, se = 0.f;
    for (int o = lane; o < D_EMB; o += 32) {
        float ev = emb[(size_t)w * D_EMB + o];
        s = fmaf(ev, g_b1eff[o] - 0.5f * ev, s);
        se = __fadd_rn(se, __fmul_rn(ev, ev));
    }
#pragma unroll
    for (int d = 16; d >= 1; d >>= 1) {
        s += __shfl_xor_sync(0xffffffffu, s, d);
        se = __fadd_rn(se, __shfl_xor_sync(0xffffffffu, se, d));
    }
    if (lane == 0) { g_c[w] = s; g_se[w] = se; }
}

// ---------------- K2: approx scores (packed f32x2 FMA) + candidates ----------
// s[t,k] = flat[t,:].A[k,:] + c[k]. FFMA2: 64 MACs per 27 issue slots.
__global__ __launch_bounds__(256, 2) void k2_argmax(const float* __restrict__ inputs) {
    extern __shared__ float smem[];
    float* sFlat = smem;                 // [256 kk][FPAD]
    float* sA = smem + D_IN * FPAD;      // [64 kk][APAD]
    int* sCnt = (int*)(smem + D_IN * FPAD + KK_CHUNK * APAD);
    int* sCand = sCnt + 64;              // [64][16]

    const int t = threadIdx.x;
    const int t0 = blockIdx.x * TOK_TILE;

    if (t < 64) sCnt[t] = 0;

    {
        int tok = t & 63;
        int qb = t >> 6;
        const float* rowp = inputs + (size_t)(t0 + tok) * D_IN;
#pragma unroll
        for (int pass = 0; pass < 16; pass++) {
            int q = qb + pass * 4;
            float4 v = *(const float4*)(rowp + q * 4);
            sFlat[(q * 4 + 0) * FPAD + tok] = v.x;
            sFlat[(q * 4 + 1) * FPAD + tok] = v.y;
            sFlat[(q * 4 + 2) * FPAD + tok] = v.z;
            sFlat[(q * 4 + 3) * FPAD + tok] = v.w;
        }
    }

    const int cbg = t & 15;    // 8 codewords (4 f32x2 pairs)
    const int tokg = t >> 4;   // 4 tokens
    float v0[4], v1[4], v2[4];
    int i0[4], i1[4], i2[4];
#pragma unroll
    for (int u = 0; u < 4; u++) {
        v0[u] = v1[u] = v2[u] = -INFINITY;
        i0[u] = i1[u] = i2[u] = 0;
    }

    for (int cb0 = 0; cb0 < K_CB; cb0 += CB_TILE) {
        u64 acc2[4][4];   // [cw pair][token], each lane one fp32 acc
#pragma unroll
        for (int i = 0; i < 4; i++)
#pragma unroll
            for (int u = 0; u < 4; u++) acc2[i][u] = 0ull;

        for (int kk0 = 0; kk0 < D_IN; kk0 += KK_CHUNK) {
            __syncthreads();
            {
                int cv = t & 31;
                int kr = t >> 5;
#pragma unroll
                for (int pass = 0; pass < 8; pass++) {
                    int kk = kr + pass * 8;
                    float4 v = *(const float4*)&g_AT[(size_t)(kk0 + kk) * K_CB + cb0 + cv * 4];
                    *(float4*)&sA[kk * APAD + cv * 4] = v;
                }
            }
            __syncthreads();
#pragma unroll 2
            for (int kk = 0; kk < KK_CHUNK; kk++) {
                const float4 a = *(const float4*)(sFlat + (kk0 + kk) * FPAD + (tokg << 2));
                // codeword pairs arrive pre-packed as 64-bit lanes
                const ulonglong2 bA = *(const ulonglong2*)(sA + kk * APAD + (cbg << 3));
                const ulonglong2 bB = *(const ulonglong2*)(sA + kk * APAD + (cbg << 3) + 4);
                u64 bb[4] = {bA.x, bA.y, bB.x, bB.y};
                u64 aa[4];
                {
                    unsigned int ax = __float_as_uint(a.x), ay = __float_as_uint(a.y);
                    unsigned int az = __float_as_uint(a.z), aw = __float_as_uint(a.w);
                    asm("mov.b64 %0, {%1, %1};" : "=l"(aa[0]) : "r"(ax));
                    asm("mov.b64 %0, {%1, %1};" : "=l"(aa[1]) : "r"(ay));
                    asm("mov.b64 %0, {%1, %1};" : "=l"(aa[2]) : "r"(az));
                    asm("mov.b64 %0, {%1, %1};" : "=l"(aa[3]) : "r"(aw));
                }
#pragma unroll
                for (int i = 0; i < 4; i++)
#pragma unroll
                    for (int u = 0; u < 4; u++)
                        asm("fma.rn.f32x2 %0, %1, %2, %0;"
                            : "+l"(acc2[i][u]) : "l"(bb[i]), "l"(aa[u]));
            }
        }
        // unpack, add bias, top-3 insertion per (thread, token)
#pragma unroll
        for (int i = 0; i < 4; i++) {
            int cbp = cb0 + cbg * 8 + i * 2;
            float c_lo = g_c[cbp], c_hi = g_c[cbp + 1];
#pragma unroll
            for (int u = 0; u < 4; u++) {
                float lo, hi;
                asm("mov.b64 {%0, %1}, %2;" : "=f"(lo), "=f"(hi) : "l"(acc2[i][u]));
                float s0 = lo + c_lo;
                float s1 = hi + c_hi;
#pragma unroll
                for (int h = 0; h < 2; h++) {
                    float s = h ? s1 : s0;
                    int cb = cbp + h;
                    if (s > v2[u]) {
                        if (s > v1[u]) {
                            if (s > v0[u]) {
                                v2[u]=v1[u]; i2[u]=i1[u]; v1[u]=v0[u]; i1[u]=i0[u];
                                v0[u]=s; i0[u]=cb;
                            } else { v2[u]=v1[u]; i2[u]=i1[u]; v1[u]=s; i1[u]=cb; }
                        } else { v2[u]=s; i2[u]=cb; }
                    }
                }
            }
        }
    }

    // per-token global max over the 16 cb groups, then emit candidates
#pragma unroll
    for (int u = 0; u < 4; u++) {
        float g = v0[u];
#pragma unroll
        for (int d = 8; d >= 1; d >>= 1)
            g = fmaxf(g, __shfl_down_sync(0xffffffffu, g, d, 16));
        g = __shfl_sync(0xffffffffu, g, 0, 16);
        float thr = g - MARGIN;
        int tokl = tokg * 4 + u;
        if (v0[u] >= thr) { int p = atomicAdd(&sCnt[tokl], 1); if (p < 16) sCand[tokl * 16 + p] = i0[u]; }
        if (v1[u] >= thr) { int p = atomicAdd(&sCnt[tokl], 1); if (p < 16) sCand[tokl * 16 + p] = i1[u]; }
        if (v2[u] >= thr) { int p = atomicAdd(&sCnt[tokl], 1); if (p < 16) sCand[tokl * 16 + p] = i2[u]; }
    }
    __syncthreads();
    if (t < 64) {
        int cnt = sCnt[t];
        int tok = t0 + t;
        g_ccount[tok] = cnt;
        if (cnt == 1) {
            int k = sCand[t * 16];
            g_idx[tok] = k;
            atomicAdd(&g_hist[k], 1u);
        } else {
            int m = cnt < 16 ? cnt : 16;
            for (int j = 0; j < m; j++) g_cand[tok][j] = (unsigned short)sCand[t * 16 + j];
            int p = atomicAdd(&g_nneedy, 1);
            g_needy[p] = tok;
        }
    }
}

// ---------------- K_exact: jax-emulated fp32 distances for contested tokens --
__global__ __launch_bounds__(256) void k_exact(
    const float* __restrict__ inputs, const float* __restrict__ g1v,
    const float* __restrict__ beta1, const float* __restrict__ W1,
    const float* __restrict__ b1, const float* __restrict__ emb, float S) {
    __shared__ float sXin[D_IN];
    __shared__ float sX[D_EMB];
    __shared__ float sRed[256];
    __shared__ int sRedI[256];
    __shared__ float sSx;
    const int tid = threadIdx.x;
    const int n = g_nneedy;
    for (int it = blockIdx.x; it < n; it += gridDim.x) {
        int t = g_needy[it];
        {
            float f = inputs[(size_t)t * D_IN + tid];
            float sc = __fmul_rn(g1v[tid], S);
            sXin[tid] = __fadd_rn(__fmul_rn(f, sc), beta1[tid]);
        }
        __syncthreads();
#pragma unroll
        for (int h = 0; h < 2; h++) {
            int o = tid + h * 256;
            const float4* w4 = (const float4*)(W1 + (size_t)o * D_IN);
            float a = 0.f;
#pragma unroll 4
            for (int i4 = 0; i4 < D_IN / 4; i4++) {
                float4 w = w4[i4];
                a = fmaf(sXin[i4 * 4 + 0], w.x, a);
                a = fmaf(sXin[i4 * 4 + 1], w.y, a);
                a = fmaf(sXin[i4 * 4 + 2], w.z, a);
                a = fmaf(sXin[i4 * 4 + 3], w.w, a);
            }
            sX[o] = __fadd_rn(a, b1[o]);
        }
        __syncthreads();
        {
            float p = __fadd_rn(__fmul_rn(sX[tid], sX[tid]),
                                __fmul_rn(sX[tid + 256], sX[tid + 256]));
#pragma unroll
            for (int d = 16; d >= 1; d >>= 1)
                p = __fadd_rn(p, __shfl_xor_sync(0xffffffffu, p, d));
            if ((tid & 31) == 0) sRed[tid >> 5] = p;
            __syncthreads();
            if (tid == 0) {
                float s = 0.f;
#pragma unroll
                for (int w = 0; w < 8; w++) s = __fadd_rn(s, sRed[w]);
                sSx = s;
            }
            __syncthreads();
        }
        float sx = sSx;
        int cnt = g_ccount[t];
        int C = (cnt <= 16) ? cnt : K_CB;
        float bd = INFINITY;
        int bk = 0x7fffffff;
        for (int ci = tid; ci < C; ci += 256) {
            int k = (cnt <= 16) ? (int)g_cand[t][ci] : ci;
            const float4* e4 = (const float4*)(emb + (size_t)k * D_EMB);
            float m = 0.f;
#pragma unroll 4
            for (int o4 = 0; o4 < D_EMB / 4; o4++) {
                float4 e = e4[o4];
                m = fmaf(sX[o4 * 4 + 0], e.x, m);
                m = fmaf(sX[o4 * 4 + 1], e.y, m);
                m = fmaf(sX[o4 * 4 + 2], e.z, m);
                m = fmaf(sX[o4 * 4 + 3], e.w, m);
            }
            float d = __fsub_rn(__fadd_rn(sx, g_se[k]), __fmul_rn(2.0f, m));
            if (d < bd || (d == bd && k < bk)) { bd = d; bk = k; }
        }
        sRed[tid] = bd; sRedI[tid] = bk;
        __syncthreads();
        for (int d = 128; d >= 1; d >>= 1) {
            if (tid < d) {
                float od = sRed[tid + d]; int ok = sRedI[tid + d];
                if (od < sRed[tid] || (od == sRed[tid] && ok < sRedI[tid])) {
                    sRed[tid] = od; sRedI[tid] = ok;
                }
            }
            __syncthreads();
        }
        if (tid == 0) { g_idx[t] = sRedI[0]; atomicAdd(&g_hist[sRedI[0]], 1u); }
        __syncthreads();
    }
}

// ---------------- K3: gather Q[idx], straight-through output, SSE partials ---
__global__ __launch_bounds__(256) void k3_gather(const float* __restrict__ inputs,
                                                 float* __restrict__ outq) {
    const int t = threadIdx.x;
    float s = 0.f;
#pragma unroll
    for (int r = 0; r < 8; r++) {
        int gid = blockIdx.x * 2048 + r * 256 + t;
        int tok = gid >> 8;
        int j = gid & 255;
        int idx = g_idx[tok];
        float q = g_Q[(size_t)idx * D_IN + j];
        float x = inputs[gid];
        float d = __fsub_rn(q, x);
        outq[gid] = __fadd_rn(x, d);
        s = fmaf(d, d, s);
    }
#pragma unroll
    for (int d = 16; d >= 1; d >>= 1) s += __shfl_xor_sync(0xffffffffu, s, d);
    __shared__ float wsum[8];
    if ((t & 31) == 0) wsum[t >> 5] = s;
    __syncthreads();
    if (t == 0) {
        float tot = 0.f;
#pragma unroll
        for (int w = 0; w < 8; w++) tot += wsum[w];
        g_partial[blockIdx.x] = (double)tot;
    }
}

// ---------------- K4: loss + usage -------------------------------------------
__global__ void k4_final(float* __restrict__ out, int T) {
    int t = blockIdx.x * 256 + threadIdx.x;
    if (t < K_CB) out[1 + (size_t)T * D_IN + t] = (float)g_hist[t] * (1.0f / (float)T);
    if (blockIdx.x == 0) {
        double s = 0.0;
        for (int i = threadIdx.x; i < 8192; i += 256) s += g_partial[i];
        __shared__ double sh[256];
        sh[threadIdx.x] = s;
        __syncthreads();
        for (int d = 128; d >= 1; d >>= 1) {
            if (threadIdx.x < d) sh[threadIdx.x] += sh[threadIdx.x + d];
            __syncthreads();
        }
        if (threadIdx.x == 0)
            out[0] = (float)(1.25 * sh[0] / ((double)T * (double)D_IN));
    }
}

// ---------------- launch ------------------------------------------------------
extern "C" void kernel_launch(void* const* d_in, const int* in_sizes, int n_in,
                              void* d_out, int out_size) {
    const float* inputs    = (const float*)d_in[0];
    const float* bn1_gamma = (const float*)d_in[1];
    const float* bn1_beta  = (const float*)d_in[2];
    const float* W1        = (const float*)d_in[3];
    const float* b1        = (const float*)d_in[4];
    const float* emb       = (const float*)d_in[5];
    const float* bn2_gamma = (const float*)d_in[6];
    const float* bn2_beta  = (const float*)d_in[7];
    const float* W2        = (const float*)d_in[8];
    const float* b2        = (const float*)d_in[9];
    float* out = (float*)d_out;
    const int T = in_sizes[0] / D_IN;   // 65536

    float af = (float)(1.0 + 1e-5);
    float S = 1.0f / sqrtf(af);

    k0_init<<<8, 256>>>(W1, b1, bn1_beta);
    k1_precompute<<<K_CB / K1_ROWS, 256>>>(emb, W1, W2, bn1_gamma, bn2_gamma, bn2_beta, b2);
    k1b_c<<<K_CB / 8, 256>>>(emb);
    cudaFuncSetAttribute(k2_argmax, cudaFuncAttributeMaxDynamicSharedMemorySize, K2_SMEM);
    k2_argmax<<<T / TOK_TILE, 256, K2_SMEM>>>(inputs);
    k_exact<<<NB_EXACT, 256>>>(inputs, bn1_gamma, bn1_beta, W1, b1, emb, S);
    k3_gather<<<8192, 256>>>(inputs, out + 1);
    k4_final<<<8, 256>>>(out, T);
}

// round 6
// speedup vs baseline: 1.1894x; 1.1894x over previous
#include <cuda_runtime.h>
#include <math.h>

#define D_IN   256
#define D_EMB  512
#define K_CB   2048
#define T_MAX  65536

#define TOK_TILE 64
#define CB_TILE  128
#define KK_CHUNK 64
#define FPAD 68
#define APAD 132
#define K2_SMEM ((D_IN * FPAD + KK_CHUNK * APAD) * 4 + 64 * 4 + 64 * 16 * 4)
#define MARGIN 1.4e-4f
#define NB_EXACT 2048

typedef unsigned long long u64;

// ---------------- scratch (device globals; no allocations allowed) -----------
__device__ __align__(16) float g_AT[D_IN * K_CB];   // A transposed [i][k]
__device__ __align__(16) float g_Q[K_CB * D_IN];    // fused output codebook [k][j]
__device__ __align__(16) float g_W1T[D_IN * D_EMB]; // W1 transposed [i][o]
__device__ __align__(16) float g_W2T[D_EMB * D_IN]; // W2 transposed [o][j]
__device__ float g_c[K_CB];
__device__ float g_se[K_CB];
__device__ float g_b1eff[D_EMB];
__device__ int g_idx[T_MAX];
__device__ unsigned int g_hist[K_CB];
__device__ double g_partial[8192];
__device__ int g_ccount[T_MAX];
__device__ unsigned short g_cand[T_MAX][16];
__device__ int g_needy[T_MAX];
__device__ int g_nneedy;

// ---------------- KT: tiled transpose ----------------------------------------
__global__ void kT_transpose(const float* __restrict__ src, float* __restrict__ dst,
                             int R, int C) {
    __shared__ float tile[32][33];
    int bx = blockIdx.x * 32, by = blockIdx.y * 32;
    int x = bx + threadIdx.x;
    int y = by + threadIdx.y;
#pragma unroll
    for (int j = 0; j < 32; j += 8)
        if (y + j < R && x < C) tile[threadIdx.y + j][threadIdx.x] = src[(size_t)(y + j) * C + x];
    __syncthreads();
    x = by + threadIdx.x;
    y = bx + threadIdx.y;
#pragma unroll
    for (int j = 0; j < 32; j += 8)
        if (y + j < C && x < R) dst[(size_t)(y + j) * R + x] = tile[threadIdx.x][threadIdx.y + j];
}

// ---------------- K0: b1eff (coalesced via W1T), zero hist -------------------
__global__ void k0_init(const float* __restrict__ b1, const float* __restrict__ beta1) {
    int t = blockIdx.x * blockDim.x + threadIdx.x;
    if (t < D_EMB) {
        float s = b1[t];
        for (int i = 0; i < D_IN; i++) s = fmaf(beta1[i], g_W1T[(size_t)i * D_EMB + t], s);
        g_b1eff[t] = s;
    }
    if (t < K_CB) g_hist[t] = 0u;
    if (t == 0) g_nneedy = 0;
}

// ---------------- K1: precompute AT and Q ------------------------------------
#define K1_ROWS 16
#define EPAD 20
__global__ __launch_bounds__(256) void k1_precompute(
    const float* __restrict__ emb, const float* __restrict__ W1,
    const float* __restrict__ g1v, const float* __restrict__ g2v,
    const float* __restrict__ beta2, const float* __restrict__ b2) {
    __shared__ float sE[D_EMB * EPAD];
    __shared__ float sG2[D_EMB];
    __shared__ float sB2[D_EMB];
    const int t = threadIdx.x;
    const int k0 = blockIdx.x * K1_ROWS;
    const float bn_s = rsqrtf(1.0f + 1e-5f);

    {
        int r = t & 15, ov = t >> 4;
        for (int pass = 0; pass < 8; pass++) {
            int o4 = ov + pass * 16;
            float4 v = *(const float4*)&emb[(size_t)(k0 + r) * D_EMB + o4 * 4];
            sE[(o4 * 4 + 0) * EPAD + r] = v.x;
            sE[(o4 * 4 + 1) * EPAD + r] = v.y;
            sE[(o4 * 4 + 2) * EPAD + r] = v.z;
            sE[(o4 * 4 + 3) * EPAD + r] = v.w;
        }
    }
    for (int i = t; i < D_EMB; i += 256) {
        sG2[i] = g2v[i] * bn_s;
        sB2[i] = beta2[i];
    }
    __syncthreads();

    const int j = t;
    float accA[16], accQ[16];
    float qc = 0.f;
#pragma unroll
    for (int r = 0; r < 16; r++) { accA[r] = 0.f; accQ[r] = 0.f; }

#pragma unroll 2
    for (int o = 0; o < D_EMB; o++) {
        float w1 = W1[(size_t)o * D_IN + j];
        float w2 = g_W2T[(size_t)o * D_IN + j];   // coalesced
        float gw = sG2[o] * w2;
        qc = fmaf(sB2[o], w2, qc);
        const float* e = &sE[o * EPAD];
        float4 e0 = *(const float4*)(e + 0);
        float4 e1 = *(const float4*)(e + 4);
        float4 e2 = *(const float4*)(e + 8);
        float4 e3 = *(const float4*)(e + 12);
        float ev[16] = {e0.x,e0.y,e0.z,e0.w, e1.x,e1.y,e1.z,e1.w,
                        e2.x,e2.y,e2.z,e2.w, e3.x,e3.y,e3.z,e3.w};
#pragma unroll
        for (int r = 0; r < 16; r++) {
            accA[r] = fmaf(ev[r], w1, accA[r]);
            accQ[r] = fmaf(ev[r], gw, accQ[r]);
        }
    }
    float g1j = g1v[j] * bn_s;
    float b2j = b2[j];
#pragma unroll
    for (int r4 = 0; r4 < 4; r4++) {
        float4 va;
        va.x = g1j * accA[r4*4+0]; va.y = g1j * accA[r4*4+1];
        va.z = g1j * accA[r4*4+2]; va.w = g1j * accA[r4*4+3];
        *(float4*)&g_AT[(size_t)j * K_CB + k0 + r4 * 4] = va;
    }
#pragma unroll
    for (int r = 0; r < 16; r++)
        g_Q[(size_t)(k0 + r) * D_IN + j] = accQ[r] + qc + b2j;
}

// ---------------- K1b: c[k] and se[k] ----------------------------------------
__global__ __launch_bounds__(256) void k1b_c(const float* __restrict__ emb) {
    int w = blockIdx.x * 8 + (threadIdx.x >> 5);
    int lane = threadIdx.x & 31;
    if (w >= K_CB) return;
    float s = 0.f, se = 0.f;
    for (int o = lane; o < D_EMB; o += 32) {
        float ev = emb[(size_t)w * D_EMB + o];
        s = fmaf(ev, g_b1eff[o] - 0.5f * ev, s);
        se = __fadd_rn(se, __fmul_rn(ev, ev));
    }
#pragma unroll
    for (int d = 16; d >= 1; d >>= 1) {
        s += __shfl_xor_sync(0xffffffffu, s, d);
        se = __fadd_rn(se, __shfl_xor_sync(0xffffffffu, se, d));
    }
    if (lane == 0) { g_c[w] = s; g_se[w] = se; }
}

// ---------------- K2: approx scores (FFMA2 + batched operand prefetch) -------
__global__ __launch_bounds__(256, 2) void k2_argmax(const float* __restrict__ inputs) {
    extern __shared__ float smem[];
    float* sFlat = smem;                 // [256 kk][FPAD]
    float* sA = smem + D_IN * FPAD;      // [64 kk][APAD]
    int* sCnt = (int*)(smem + D_IN * FPAD + KK_CHUNK * APAD);
    int* sCand = sCnt + 64;              // [64][16]

    const int t = threadIdx.x;
    const int t0 = blockIdx.x * TOK_TILE;

    if (t < 64) sCnt[t] = 0;

    {
        int tok = t & 63;
        int qb = t >> 6;
        const float* rowp = inputs + (size_t)(t0 + tok) * D_IN;
#pragma unroll
        for (int pass = 0; pass < 16; pass++) {
            int q = qb + pass * 4;
            float4 v = *(const float4*)(rowp + q * 4);
            sFlat[(q * 4 + 0) * FPAD + tok] = v.x;
            sFlat[(q * 4 + 1) * FPAD + tok] = v.y;
            sFlat[(q * 4 + 2) * FPAD + tok] = v.z;
            sFlat[(q * 4 + 3) * FPAD + tok] = v.w;
        }
    }

    const int cbg = t & 15;    // 8 codewords (4 f32x2 pairs)
    const int tokg = t >> 4;   // 4 tokens
    float v0[4], v1[4], v2[4];
    int i0[4], i1[4], i2[4];
#pragma unroll
    for (int u = 0; u < 4; u++) {
        v0[u] = v1[u] = v2[u] = -INFINITY;
        i0[u] = i1[u] = i2[u] = 0;
    }

    for (int cb0 = 0; cb0 < K_CB; cb0 += CB_TILE) {
        u64 acc2[4][4];
#pragma unroll
        for (int i = 0; i < 4; i++)
#pragma unroll
            for (int u = 0; u < 4; u++) acc2[i][u] = 0ull;

        for (int kk0 = 0; kk0 < D_IN; kk0 += KK_CHUNK) {
            __syncthreads();
            {
                int cv = t & 31;
                int kr = t >> 5;
#pragma unroll
                for (int pass = 0; pass < 8; pass++) {
                    int kk = kr + pass * 8;
                    float4 v = *(const float4*)&g_AT[(size_t)(kk0 + kk) * K_CB + cb0 + cv * 4];
                    *(float4*)&sA[kk * APAD + cv * 4] = v;
                }
            }
            __syncthreads();
#pragma unroll 2
            for (int kq = 0; kq < KK_CHUNK; kq += 4) {
                // batch all operand LDS for 4 kk steps up front (MLP=12)
                float4 a4[4];
                ulonglong2 bA[4], bB[4];
#pragma unroll
                for (int j = 0; j < 4; j++) {
                    int kk = kq + j;
                    a4[j] = *(const float4*)(sFlat + (kk0 + kk) * FPAD + (tokg << 2));
                    bA[j] = *(const ulonglong2*)(sA + kk * APAD + (cbg << 3));
                    bB[j] = *(const ulonglong2*)(sA + kk * APAD + (cbg << 3) + 4);
                }
#pragma unroll
                for (int j = 0; j < 4; j++) {
                    u64 aa[4];
                    {
                        unsigned int ax = __float_as_uint(a4[j].x), ay = __float_as_uint(a4[j].y);
                        unsigned int az = __float_as_uint(a4[j].z), aw = __float_as_uint(a4[j].w);
                        asm("mov.b64 %0, {%1, %1};" : "=l"(aa[0]) : "r"(ax));
                        asm("mov.b64 %0, {%1, %1};" : "=l"(aa[1]) : "r"(ay));
                        asm("mov.b64 %0, {%1, %1};" : "=l"(aa[2]) : "r"(az));
                        asm("mov.b64 %0, {%1, %1};" : "=l"(aa[3]) : "r"(aw));
                    }
                    u64 bb[4] = {bA[j].x, bA[j].y, bB[j].x, bB[j].y};
#pragma unroll
                    for (int i = 0; i < 4; i++)
#pragma unroll
                        for (int u = 0; u < 4; u++)
                            asm("fma.rn.f32x2 %0, %1, %2, %0;"
                                : "+l"(acc2[i][u]) : "l"(bb[i]), "l"(aa[u]));
                }
            }
        }
#pragma unroll
        for (int i = 0; i < 4; i++) {
            int cbp = cb0 + cbg * 8 + i * 2;
            float c_lo = g_c[cbp], c_hi = g_c[cbp + 1];
#pragma unroll
            for (int u = 0; u < 4; u++) {
                float lo, hi;
                asm("mov.b64 {%0, %1}, %2;" : "=f"(lo), "=f"(hi) : "l"(acc2[i][u]));
                float s0 = lo + c_lo;
                float s1 = hi + c_hi;
#pragma unroll
                for (int h = 0; h < 2; h++) {
                    float s = h ? s1 : s0;
                    int cb = cbp + h;
                    if (s > v2[u]) {
                        if (s > v1[u]) {
                            if (s > v0[u]) {
                                v2[u]=v1[u]; i2[u]=i1[u]; v1[u]=v0[u]; i1[u]=i0[u];
                                v0[u]=s; i0[u]=cb;
                            } else { v2[u]=v1[u]; i2[u]=i1[u]; v1[u]=s; i1[u]=cb; }
                        } else { v2[u]=s; i2[u]=cb; }
                    }
                }
            }
        }
    }

#pragma unroll
    for (int u = 0; u < 4; u++) {
        float g = v0[u];
#pragma unroll
        for (int d = 8; d >= 1; d >>= 1)
            g = fmaxf(g, __shfl_down_sync(0xffffffffu, g, d, 16));
        g = __shfl_sync(0xffffffffu, g, 0, 16);
        float thr = g - MARGIN;
        int tokl = tokg * 4 + u;
        if (v0[u] >= thr) { int p = atomicAdd(&sCnt[tokl], 1); if (p < 16) sCand[tokl * 16 + p] = i0[u]; }
        if (v1[u] >= thr) { int p = atomicAdd(&sCnt[tokl], 1); if (p < 16) sCand[tokl * 16 + p] = i1[u]; }
        if (v2[u] >= thr) { int p = atomicAdd(&sCnt[tokl], 1); if (p < 16) sCand[tokl * 16 + p] = i2[u]; }
    }
    __syncthreads();
    if (t < 64) {
        int cnt = sCnt[t];
        int tok = t0 + t;
        g_ccount[tok] = cnt;
        if (cnt == 1) {
            int k = sCand[t * 16];
            g_idx[tok] = k;
            atomicAdd(&g_hist[k], 1u);
        } else {
            int m = cnt < 16 ? cnt : 16;
            for (int j = 0; j < m; j++) g_cand[tok][j] = (unsigned short)sCand[t * 16 + j];
            int p = atomicAdd(&g_nneedy, 1);
            g_needy[p] = tok;
        }
    }
}

// ---------------- K_exact: jax-emulated fp32 distances for contested tokens --
// x-pass now reads W1T (coalesced LDG.128); per-output FMA chain order UNCHANGED.
__global__ __launch_bounds__(256) void k_exact(
    const float* __restrict__ inputs, const float* __restrict__ g1v,
    const float* __restrict__ beta1, const float* __restrict__ b1,
    const float* __restrict__ emb, float S) {
    __shared__ float sXin[D_IN];
    __shared__ float sX[D_EMB];
    __shared__ float sRed[256];
    __shared__ int sRedI[256];
    __shared__ float sSx;
    const int tid = threadIdx.x;
    const int n = g_nneedy;
    for (int it = blockIdx.x; it < n; it += gridDim.x) {
        int t = g_needy[it];
        {
            float f = inputs[(size_t)t * D_IN + tid];
            float sc = __fmul_rn(g1v[tid], S);
            sXin[tid] = __fadd_rn(__fmul_rn(f, sc), beta1[tid]);
        }
        __syncthreads();
        // x rows: threads 0..127, each 4 consecutive outputs, coalesced W1T reads
        if (tid < 128) {
            int ob = tid * 4;
            float a0 = 0.f, a1 = 0.f, a2 = 0.f, a3 = 0.f;
#pragma unroll 4
            for (int i = 0; i < D_IN; i++) {
                float xi = sXin[i];
                float4 w = *(const float4*)(g_W1T + (size_t)i * D_EMB + ob);
                a0 = fmaf(xi, w.x, a0);
                a1 = fmaf(xi, w.y, a1);
                a2 = fmaf(xi, w.z, a2);
                a3 = fmaf(xi, w.w, a3);
            }
            sX[ob + 0] = __fadd_rn(a0, b1[ob + 0]);
            sX[ob + 1] = __fadd_rn(a1, b1[ob + 1]);
            sX[ob + 2] = __fadd_rn(a2, b1[ob + 2]);
            sX[ob + 3] = __fadd_rn(a3, b1[ob + 3]);
        }
        __syncthreads();
        {
            float p = __fadd_rn(__fmul_rn(sX[tid], sX[tid]),
                                __fmul_rn(sX[tid + 256], sX[tid + 256]));
#pragma unroll
            for (int d = 16; d >= 1; d >>= 1)
                p = __fadd_rn(p, __shfl_xor_sync(0xffffffffu, p, d));
            if ((tid & 31) == 0) sRed[tid >> 5] = p;
            __syncthreads();
            if (tid == 0) {
                float s = 0.f;
#pragma unroll
                for (int w = 0; w < 8; w++) s = __fadd_rn(s, sRed[w]);
                sSx = s;
            }
            __syncthreads();
        }
        float sx = sSx;
        int cnt = g_ccount[t];
        int C = (cnt <= 16) ? cnt : K_CB;
        float bd = INFINITY;
        int bk = 0x7fffffff;
        for (int ci = tid; ci < C; ci += 256) {
            int k = (cnt <= 16) ? (int)g_cand[t][ci] : ci;
            const float4* e4 = (const float4*)(emb + (size_t)k * D_EMB);
            float m = 0.f;
#pragma unroll 4
            for (int o4 = 0; o4 < D_EMB / 4; o4++) {
                float4 e = e4[o4];
                m = fmaf(sX[o4 * 4 + 0], e.x, m);
                m = fmaf(sX[o4 * 4 + 1], e.y, m);
                m = fmaf(sX[o4 * 4 + 2], e.z, m);
                m = fmaf(sX[o4 * 4 + 3], e.w, m);
            }
            float d = __fsub_rn(__fadd_rn(sx, g_se[k]), __fmul_rn(2.0f, m));
            if (d < bd || (d == bd && k < bk)) { bd = d; bk = k; }
        }
        sRed[tid] = bd; sRedI[tid] = bk;
        __syncthreads();
        for (int d = 128; d >= 1; d >>= 1) {
            if (tid < d) {
                float od = sRed[tid + d]; int ok = sRedI[tid + d];
                if (od < sRed[tid] || (od == sRed[tid] && ok < sRedI[tid])) {
                    sRed[tid] = od; sRedI[tid] = ok;
                }
            }
            __syncthreads();
        }
        if (tid == 0) { g_idx[t] = sRedI[0]; atomicAdd(&g_hist[sRedI[0]], 1u); }
        __syncthreads();
    }
}

// ---------------- K3: gather Q[idx], straight-through output, SSE partials ---
__global__ __launch_bounds__(256) void k3_gather(const float* __restrict__ inputs,
                                                 float* __restrict__ outq) {
    const int t = threadIdx.x;
    float s = 0.f;
#pragma unroll
    for (int r = 0; r < 8; r++) {
        int gid = blockIdx.x * 2048 + r * 256 + t;
        int tok = gid >> 8;
        int j = gid & 255;
        int idx = g_idx[tok];
        float q = g_Q[(size_t)idx * D_IN + j];
        float x = inputs[gid];
        float d = __fsub_rn(q, x);
        outq[gid] = __fadd_rn(x, d);
        s = fmaf(d, d, s);
    }
#pragma unroll
    for (int d = 16; d >= 1; d >>= 1) s += __shfl_xor_sync(0xffffffffu, s, d);
    __shared__ float wsum[8];
    if ((t & 31) == 0) wsum[t >> 5] = s;
    __syncthreads();
    if (t == 0) {
        float tot = 0.f;
#pragma unroll
        for (int w = 0; w < 8; w++) tot += wsum[w];
        g_partial[blockIdx.x] = (double)tot;
    }
}

// ---------------- K4: loss + usage -------------------------------------------
__global__ void k4_final(float* __restrict__ out, int T) {
    int t = blockIdx.x * 256 + threadIdx.x;
    if (t < K_CB) out[1 + (size_t)T * D_IN + t] = (float)g_hist[t] * (1.0f / (float)T);
    if (blockIdx.x == 0) {
        double s = 0.0;
        for (int i = threadIdx.x; i < 8192; i += 256) s += g_partial[i];
        __shared__ double sh[256];
        sh[threadIdx.x] = s;
        __syncthreads();
        for (int d = 128; d >= 1; d >>= 1) {
            if (threadIdx.x < d) sh[threadIdx.x] += sh[threadIdx.x + d];
            __syncthreads();
        }
        if (threadIdx.x == 0)
            out[0] = (float)(1.25 * sh[0] / ((double)T * (double)D_IN));
    }
}

// ---------------- launch ------------------------------------------------------
extern "C" void kernel_launch(void* const* d_in, const int* in_sizes, int n_in,
                              void* d_out, int out_size) {
    const float* inputs    = (const float*)d_in[0];
    const float* bn1_gamma = (const float*)d_in[1];
    const float* bn1_beta  = (const float*)d_in[2];
    const float* W1        = (const float*)d_in[3];
    const float* b1        = (const float*)d_in[4];
    const float* emb       = (const float*)d_in[5];
    const float* bn2_gamma = (const float*)d_in[6];
    const float* bn2_beta  = (const float*)d_in[7];
    const float* W2        = (const float*)d_in[8];
    const float* b2        = (const float*)d_in[9];
    float* out = (float*)d_out;
    const int T = in_sizes[0] / D_IN;   // 65536

    float af = (float)(1.0 + 1e-5);
    float S = 1.0f / sqrtf(af);

    float* w1t; cudaGetSymbolAddress((void**)&w1t, g_W1T);
    float* w2t; cudaGetSymbolAddress((void**)&w2t, g_W2T);

    {   // transposes: W1 [512x256] -> W1T [256x512]; W2 [256x512] -> W2T [512x256]
        dim3 blk(32, 8);
        kT_transpose<<<dim3(D_IN / 32, D_EMB / 32), blk>>>(W1, w1t, D_EMB, D_IN);
        kT_transpose<<<dim3(D_EMB / 32, D_IN / 32), blk>>>(W2, w2t, D_IN, D_EMB);
    }
    k0_init<<<8, 256>>>(b1, bn1_beta);
    k1_precompute<<<K_CB / K1_ROWS, 256>>>(emb, W1, bn1_gamma, bn2_gamma, bn2_beta, b2);
    k1b_c<<<K_CB / 8, 256>>>(emb);
    cudaFuncSetAttribute(k2_argmax, cudaFuncAttributeMaxDynamicSharedMemorySize, K2_SMEM);
    k2_argmax<<<T / TOK_TILE, 256, K2_SMEM>>>(inputs);
    k_exact<<<NB_EXACT, 256>>>(inputs, bn1_gamma, bn1_beta, b1, emb, S);
    k3_gather<<<8192, 256>>>(inputs, out + 1);
    k4_final<<<8, 256>>>(out, T);
}

// round 8
// speedup vs baseline: 1.5847x; 1.3323x over previous
#include <cuda_runtime.h>
#include <cuda_bf16.h>
#include <mma.h>
#include <math.h>
#include <stdint.h>

using namespace nvcuda;

#define D_IN   256
#define D_EMB  512
#define K_CB   2048
#define T_MAX  65536
#define MARGIN 1.4e-4f
#define NB_EXACT 2048

#define MT   128                 // tokens per CTA
#define FLD  264                 // bf16 pitch for token/A tiles
#define OLD  132                 // float pitch for output scan buffer
#define SZ_F (MT * FLD * 2)      // 67584 bytes
#define OFF_FLO (SZ_F)
#define OFF_A   (2 * SZ_F)
#define OFF_C   (3 * SZ_F)
#define K2W_SMEM (3 * SZ_F + K_CB * 4)   // 210944

// ---------------- scratch (device globals; no allocations allowed) -----------
__device__ __align__(16) float g_Q[K_CB * D_IN];
__device__ __align__(16) float g_W1T[D_IN * D_EMB];
__device__ __align__(16) float g_W2T[D_EMB * D_IN];
__device__ __align__(16) __nv_bfloat16 g_Ahi[K_CB * D_IN];  // [cb][i] row-major
__device__ __align__(16) __nv_bfloat16 g_Alo[K_CB * D_IN];
__device__ float g_c[K_CB];
__device__ float g_se[K_CB];
__device__ float g_b1eff[D_EMB];
__device__ int g_idx[T_MAX];
__device__ unsigned int g_hist[K_CB];
__device__ double g_partial[8192];
__device__ int g_ccount[T_MAX];
__device__ unsigned short g_cand[T_MAX][16];
__device__ int g_needy[T_MAX];
__device__ int g_nneedy;

// ---------------- KT: tiled transpose ----------------------------------------
__global__ void kT_transpose(const float* __restrict__ src, float* __restrict__ dst,
                             int R, int C) {
    __shared__ float tile[32][33];
    int bx = blockIdx.x * 32, by = blockIdx.y * 32;
    int x = bx + threadIdx.x;
    int y = by + threadIdx.y;
#pragma unroll
    for (int j = 0; j < 32; j += 8)
        if (y + j < R && x < C) tile[threadIdx.y + j][threadIdx.x] = src[(size_t)(y + j) * C + x];
    __syncthreads();
    x = by + threadIdx.x;
    y = bx + threadIdx.y;
#pragma unroll
    for (int j = 0; j < 32; j += 8)
        if (y + j < C && x < R) dst[(size_t)(y + j) * R + x] = tile[threadIdx.x][threadIdx.y + j];
}

// ---------------- K0 -----------------------------------------------------------
__global__ void k0_init(const float* __restrict__ b1, const float* __restrict__ beta1) {
    int t = blockIdx.x * blockDim.x + threadIdx.x;
    if (t < D_EMB) {
        float s = b1[t];
        for (int i = 0; i < D_IN; i++) s = fmaf(beta1[i], g_W1T[(size_t)i * D_EMB + t], s);
        g_b1eff[t] = s;
    }
    if (t < K_CB) g_hist[t] = 0u;
    if (t == 0) g_nneedy = 0;
}

// ---------------- K1: precompute A (bf16 hi/lo split) and Q --------------------
#define K1_ROWS 16
#define EPAD 20
__global__ __launch_bounds__(256) void k1_precompute(
    const float* __restrict__ emb, const float* __restrict__ W1,
    const float* __restrict__ g1v, const float* __restrict__ g2v,
    const float* __restrict__ beta2, const float* __restrict__ b2) {
    __shared__ float sE[D_EMB * EPAD];
    __shared__ float sG2[D_EMB];
    __shared__ float sB2[D_EMB];
    const int t = threadIdx.x;
    const int k0 = blockIdx.x * K1_ROWS;
    const float bn_s = rsqrtf(1.0f + 1e-5f);

    {
        int r = t & 15, ov = t >> 4;
        for (int pass = 0; pass < 8; pass++) {
            int o4 = ov + pass * 16;
            float4 v = *(const float4*)&emb[(size_t)(k0 + r) * D_EMB + o4 * 4];
            sE[(o4 * 4 + 0) * EPAD + r] = v.x;
            sE[(o4 * 4 + 1) * EPAD + r] = v.y;
            sE[(o4 * 4 + 2) * EPAD + r] = v.z;
            sE[(o4 * 4 + 3) * EPAD + r] = v.w;
        }
    }
    for (int i = t; i < D_EMB; i += 256) {
        sG2[i] = g2v[i] * bn_s;
        sB2[i] = beta2[i];
    }
    __syncthreads();

    const int j = t;
    float accA[16], accQ[16];
    float qc = 0.f;
#pragma unroll
    for (int r = 0; r < 16; r++) { accA[r] = 0.f; accQ[r] = 0.f; }

#pragma unroll 2
    for (int o = 0; o < D_EMB; o++) {
        float w1 = W1[(size_t)o * D_IN + j];
        float w2 = g_W2T[(size_t)o * D_IN + j];
        float gw = sG2[o] * w2;
        qc = fmaf(sB2[o], w2, qc);
        const float* e = &sE[o * EPAD];
        float4 e0 = *(const float4*)(e + 0);
        float4 e1 = *(const float4*)(e + 4);
        float4 e2 = *(const float4*)(e + 8);
        float4 e3 = *(const float4*)(e + 12);
        float ev[16] = {e0.x,e0.y,e0.z,e0.w, e1.x,e1.y,e1.z,e1.w,
                        e2.x,e2.y,e2.z,e2.w, e3.x,e3.y,e3.z,e3.w};
#pragma unroll
        for (int r = 0; r < 16; r++) {
            accA[r] = fmaf(ev[r], w1, accA[r]);
            accQ[r] = fmaf(ev[r], gw, accQ[r]);
        }
    }
    float g1j = g1v[j] * bn_s;
    float b2j = b2[j];
#pragma unroll
    for (int r = 0; r < 16; r++) {
        float a = g1j * accA[r];
        __nv_bfloat16 hi = __float2bfloat16(a);
        __nv_bfloat16 lo = __float2bfloat16(a - __bfloat162float(hi));
        g_Ahi[(size_t)(k0 + r) * D_IN + j] = hi;   // coalesced across j
        g_Alo[(size_t)(k0 + r) * D_IN + j] = lo;
        g_Q[(size_t)(k0 + r) * D_IN + j] = accQ[r] + qc + b2j;
    }
}

// ---------------- K1b: c[k] and se[k] ------------------------------------------
__global__ __launch_bounds__(256) void k1b_c(const float* __restrict__ emb) {
    int w = blockIdx.x * 8 + (threadIdx.x >> 5);
    int lane = threadIdx.x & 31;
    if (w >= K_CB) return;
    float s = 0.f, se = 0.f;
    for (int o = lane; o < D_EMB; o += 32) {
        float ev = emb[(size_t)w * D_EMB + o];
        s = fmaf(ev, g_b1eff[o] - 0.5f * ev, s);
        se = __fadd_rn(se, __fmul_rn(ev, ev));
    }
#pragma unroll
    for (int d = 16; d >= 1; d >>= 1) {
        s += __shfl_xor_sync(0xffffffffu, s, d);
        se = __fadd_rn(se, __shfl_xor_sync(0xffffffffu, se, d));
    }
    if (lane == 0) { g_c[w] = s; g_se[w] = se; }
}

// ---------------- K2: wmma bf16 3-split score GEMM + argmax/candidates ---------
// scores = F . A^T + c ; F split (hi+lo) as bf16, A split as bf16.
// pass1: (Fhi + Flo) . Ahi   pass2: Fhi . Alo   (Flo.Alo term negligible)
__global__ __launch_bounds__(256, 1) void k2_wmma(const float* __restrict__ inputs) {
    extern __shared__ __align__(16) char smem[];
    __nv_bfloat16* sFhi = (__nv_bfloat16*)smem;
    __nv_bfloat16* sFlo = (__nv_bfloat16*)(smem + OFF_FLO);
    __nv_bfloat16* sA   = (__nv_bfloat16*)(smem + OFF_A);
    float* sOut = (float*)(smem + OFF_A);          // reuses A buffer
    float* sC   = (float*)(smem + OFF_C);
    const int tid = threadIdx.x;
    const int wid = tid >> 5;
    const int t0 = blockIdx.x * MT;
    const int tok0 = (wid & 3) * 32;   // warp token origin
    const int cb0l = (wid >> 2) * 64;  // warp local cb origin

    for (int i = tid; i < K_CB; i += 256) sC[i] = g_c[i];

    // stage tokens (bf16 hi/lo split, row-major [tok][FLD])
    for (int idx = tid; idx < MT * 64; idx += 256) {
        int tok = idx >> 6, q = idx & 63;
        float4 v = *(const float4*)&inputs[(size_t)(t0 + tok) * D_IN + q * 4];
        float f[4] = {v.x, v.y, v.z, v.w};
        uint32_t hp[2], lp[2];
#pragma unroll
        for (int pr = 0; pr < 2; pr++) {
            __nv_bfloat16 h0 = __float2bfloat16(f[pr * 2 + 0]);
            __nv_bfloat16 h1 = __float2bfloat16(f[pr * 2 + 1]);
            __nv_bfloat16 l0 = __float2bfloat16(f[pr * 2 + 0] - __bfloat162float(h0));
            __nv_bfloat16 l1 = __float2bfloat16(f[pr * 2 + 1] - __bfloat162float(h1));
            hp[pr] = (uint32_t)__bfloat16_as_ushort(h0) | ((uint32_t)__bfloat16_as_ushort(h1) << 16);
            lp[pr] = (uint32_t)__bfloat16_as_ushort(l0) | ((uint32_t)__bfloat16_as_ushort(l1) << 16);
        }
        *(uint2*)(sFhi + tok * FLD + q * 4) = make_uint2(hp[0], hp[1]);
        *(uint2*)(sFlo + tok * FLD + q * 4) = make_uint2(lp[0], lp[1]);
    }

    float v0 = -INFINITY, v1 = -INFINITY, v2 = -INFINITY;
    int i0 = 0, i1 = 0, i2 = 0;

    wmma::fragment<wmma::accumulator, 16, 16, 16, float> acc[2][4];

    for (int ct = 0; ct < 16; ct++) {
        __syncthreads();   // prev scan done; token staging done (ct==0)
        {   // copy Ahi tile [128 cb][256 k] -> sA (pitch FLD)
            const uint4* src = (const uint4*)(g_Ahi + (size_t)ct * 128 * D_IN);
            for (int i = tid; i < 128 * 32; i += 256) {
                int r = i >> 5, jj = i & 31;
                *(uint4*)((char*)sA + r * (FLD * 2) + jj * 16) = src[r * 32 + jj];
            }
        }
        __syncthreads();
#pragma unroll
        for (int mi = 0; mi < 2; mi++)
#pragma unroll
            for (int ni = 0; ni < 4; ni++) wmma::fill_fragment(acc[mi][ni], 0.0f);

        // pass 1: Fhi.Ahi + Flo.Ahi
        for (int ks = 0; ks < 16; ks++) {
            int k0 = ks * 16;
            wmma::fragment<wmma::matrix_a, 16, 16, 16, __nv_bfloat16, wmma::row_major> ah[2], al[2];
            wmma::fragment<wmma::matrix_b, 16, 16, 16, __nv_bfloat16, wmma::col_major> b[4];
#pragma unroll
            for (int mi = 0; mi < 2; mi++) {
                wmma::load_matrix_sync(ah[mi], sFhi + (tok0 + mi * 16) * FLD + k0, FLD);
                wmma::load_matrix_sync(al[mi], sFlo + (tok0 + mi * 16) * FLD + k0, FLD);
            }
#pragma unroll
            for (int ni = 0; ni < 4; ni++)
                wmma::load_matrix_sync(b[ni], sA + (cb0l + ni * 16) * FLD + k0, FLD);
#pragma unroll
            for (int ni = 0; ni < 4; ni++)
#pragma unroll
                for (int mi = 0; mi < 2; mi++) {
                    wmma::mma_sync(acc[mi][ni], ah[mi], b[ni], acc[mi][ni]);
                    wmma::mma_sync(acc[mi][ni], al[mi], b[ni], acc[mi][ni]);
                }
        }
        __syncthreads();
        {   // copy Alo tile
            const uint4* src = (const uint4*)(g_Alo + (size_t)ct * 128 * D_IN);
            for (int i = tid; i < 128 * 32; i += 256) {
                int r = i >> 5, jj = i & 31;
                *(uint4*)((char*)sA + r * (FLD * 2) + jj * 16) = src[r * 32 + jj];
            }
        }
        __syncthreads();
        // pass 2: Fhi.Alo
        for (int ks = 0; ks < 16; ks++) {
            int k0 = ks * 16;
            wmma::fragment<wmma::matrix_a, 16, 16, 16, __nv_bfloat16, wmma::row_major> ah[2];
            wmma::fragment<wmma::matrix_b, 16, 16, 16, __nv_bfloat16, wmma::col_major> b[4];
#pragma unroll
            for (int mi = 0; mi < 2; mi++)
                wmma::load_matrix_sync(ah[mi], sFhi + (tok0 + mi * 16) * FLD + k0, FLD);
#pragma unroll
            for (int ni = 0; ni < 4; ni++)
                wmma::load_matrix_sync(b[ni], sA + (cb0l + ni * 16) * FLD + k0, FLD);
#pragma unroll
            for (int ni = 0; ni < 4; ni++)
#pragma unroll
                for (int mi = 0; mi < 2; mi++)
                    wmma::mma_sync(acc[mi][ni], ah[mi], b[ni], acc[mi][ni]);
        }
        __syncthreads();   // everyone done reading sA
        // store scores to scan buffer
#pragma unroll
        for (int mi = 0; mi < 2; mi++)
#pragma unroll
            for (int ni = 0; ni < 4; ni++)
                wmma::store_matrix_sync(sOut + (tok0 + mi * 16) * OLD + cb0l + ni * 16,
                                        acc[mi][ni], OLD, wmma::mem_row_major);
        __syncthreads();
        // scan: 2 threads per token, 64 cb each, ascending index
        {
            int tok = tid >> 1, half = tid & 1;
            const float* row = sOut + tok * OLD + half * 64;
            const float* cc = sC + ct * 128 + half * 64;
            int cbb = ct * 128 + half * 64;
#pragma unroll 4
            for (int j = 0; j < 64; j++) {
                float s = row[j] + cc[j];
                if (s > v2) {
                    int cb = cbb + j;
                    if (s > v1) {
                        if (s > v0) { v2 = v1; i2 = i1; v1 = v0; i1 = i0; v0 = s; i0 = cb; }
                        else        { v2 = v1; i2 = i1; v1 = s; i1 = cb; }
                    } else          { v2 = s; i2 = cb; }
                }
            }
        }
    }

    // merge the two half-scans of each token (lexicographic: value desc, index asc)
    {
        float pv[3];
        int pi[3];
        pv[0] = __shfl_xor_sync(0xffffffffu, v0, 1); pi[0] = __shfl_xor_sync(0xffffffffu, i0, 1);
        pv[1] = __shfl_xor_sync(0xffffffffu, v1, 1); pi[1] = __shfl_xor_sync(0xffffffffu, i1, 1);
        pv[2] = __shfl_xor_sync(0xffffffffu, v2, 1); pi[2] = __shfl_xor_sync(0xffffffffu, i2, 1);
#pragma unroll
        for (int e = 0; e < 3; e++) {
            float s = pv[e]; int cb = pi[e];
            bool b0 = s > v0 || (s == v0 && cb < i0);
            bool b1 = s > v1 || (s == v1 && cb < i1);
            bool b2 = s > v2 || (s == v2 && cb < i2);
            if (b0) { v2 = v1; i2 = i1; v1 = v0; i1 = i0; v0 = s; i0 = cb; }
            else if (b1) { v2 = v1; i2 = i1; v1 = s; i1 = cb; }
            else if (b2) { v2 = s; i2 = cb; }
        }
    }
    if ((tid & 1) == 0) {
        int tok = t0 + (tid >> 1);
        float thr = v0 - MARGIN;
        if (v2 >= thr) {
            g_ccount[tok] = 17;                    // >=3 within margin -> full exact scan
            int p = atomicAdd(&g_nneedy, 1);
            g_needy[p] = tok;
        } else if (v1 >= thr) {
            g_ccount[tok] = 2;
            g_cand[tok][0] = (unsigned short)i0;
            g_cand[tok][1] = (unsigned short)i1;
            int p = atomicAdd(&g_nneedy, 1);
            g_needy[p] = tok;
        } else {
            g_ccount[tok] = 1;
            g_idx[tok] = i0;
            atomicAdd(&g_hist[i0], 1u);
        }
    }
}

// ---------------- K_exact: jax-emulated fp32 distances (UNCHANGED math) --------
__global__ __launch_bounds__(256) void k_exact(
    const float* __restrict__ inputs, const float* __restrict__ g1v,
    const float* __restrict__ beta1, const float* __restrict__ b1,
    const float* __restrict__ emb, float S) {
    __shared__ float sXin[D_IN];
    __shared__ float sX[D_EMB];
    __shared__ float sRed[256];
    __shared__ int sRedI[256];
    __shared__ float sSx;
    const int tid = threadIdx.x;
    const int n = g_nneedy;
    for (int it = blockIdx.x; it < n; it += gridDim.x) {
        int t = g_needy[it];
        {
            float f = inputs[(size_t)t * D_IN + tid];
            float sc = __fmul_rn(g1v[tid], S);
            sXin[tid] = __fadd_rn(__fmul_rn(f, sc), beta1[tid]);
        }
        __syncthreads();
        if (tid < 128) {
            int ob = tid * 4;
            float a0 = 0.f, a1 = 0.f, a2 = 0.f, a3 = 0.f;
#pragma unroll 4
            for (int i = 0; i < D_IN; i++) {
                float xi = sXin[i];
                float4 w = *(const float4*)(g_W1T + (size_t)i * D_EMB + ob);
                a0 = fmaf(xi, w.x, a0);
                a1 = fmaf(xi, w.y, a1);
                a2 = fmaf(xi, w.z, a2);
                a3 = fmaf(xi, w.w, a3);
            }
            sX[ob + 0] = __fadd_rn(a0, b1[ob + 0]);
            sX[ob + 1] = __fadd_rn(a1, b1[ob + 1]);
            sX[ob + 2] = __fadd_rn(a2, b1[ob + 2]);
            sX[ob + 3] = __fadd_rn(a3, b1[ob + 3]);
        }
        __syncthreads();
        {
            float p = __fadd_rn(__fmul_rn(sX[tid], sX[tid]),
                                __fmul_rn(sX[tid + 256], sX[tid + 256]));
#pragma unroll
            for (int d = 16; d >= 1; d >>= 1)
                p = __fadd_rn(p, __shfl_xor_sync(0xffffffffu, p, d));
            if ((tid & 31) == 0) sRed[tid >> 5] = p;
            __syncthreads();
            if (tid == 0) {
                float s = 0.f;
#pragma unroll
                for (int w = 0; w < 8; w++) s = __fadd_rn(s, sRed[w]);
                sSx = s;
            }
            __syncthreads();
        }
        float sx = sSx;
        int cnt = g_ccount[t];
        int C = (cnt <= 16) ? cnt : K_CB;
        float bd = INFINITY;
        int bk = 0x7fffffff;
        for (int ci = tid; ci < C; ci += 256) {
            int k = (cnt <= 16) ? (int)g_cand[t][ci] : ci;
            const float4* e4 = (const float4*)(emb + (size_t)k * D_EMB);
            float m = 0.f;
#pragma unroll 4
            for (int o4 = 0; o4 < D_EMB / 4; o4++) {
                float4 e = e4[o4];
                m = fmaf(sX[o4 * 4 + 0], e.x, m);
                m = fmaf(sX[o4 * 4 + 1], e.y, m);
                m = fmaf(sX[o4 * 4 + 2], e.z, m);
                m = fmaf(sX[o4 * 4 + 3], e.w, m);
            }
            float d = __fsub_rn(__fadd_rn(sx, g_se[k]), __fmul_rn(2.0f, m));
            if (d < bd || (d == bd && k < bk)) { bd = d; bk = k; }
        }
        sRed[tid] = bd; sRedI[tid] = bk;
        __syncthreads();
        for (int d = 128; d >= 1; d >>= 1) {
            if (tid < d) {
                float od = sRed[tid + d]; int ok = sRedI[tid + d];
                if (od < sRed[tid] || (od == sRed[tid] && ok < sRedI[tid])) {
                    sRed[tid] = od; sRedI[tid] = ok;
                }
            }
            __syncthreads();
        }
        if (tid == 0) { g_idx[t] = sRedI[0]; atomicAdd(&g_hist[sRedI[0]], 1u); }
        __syncthreads();
    }
}

// ---------------- K3: gather + straight-through + SSE partials -----------------
__global__ __launch_bounds__(256) void k3_gather(const float* __restrict__ inputs,
                                                 float* __restrict__ outq) {
    const int t = threadIdx.x;
    float s = 0.f;
#pragma unroll
    for (int r = 0; r < 8; r++) {
        int gid = blockIdx.x * 2048 + r * 256 + t;
        int tok = gid >> 8;
        int j = gid & 255;
        int idx = g_idx[tok];
        float q = g_Q[(size_t)idx * D_IN + j];
        float x = inputs[gid];
        float d = __fsub_rn(q, x);
        outq[gid] = __fadd_rn(x, d);
        s = fmaf(d, d, s);
    }
#pragma unroll
    for (int d = 16; d >= 1; d >>= 1) s += __shfl_xor_sync(0xffffffffu, s, d);
    __shared__ float wsum[8];
    if ((t & 31) == 0) wsum[t >> 5] = s;
    __syncthreads();
    if (t == 0) {
        float tot = 0.f;
#pragma unroll
        for (int w = 0; w < 8; w++) tot += wsum[w];
        g_partial[blockIdx.x] = (double)tot;
    }
}

// ---------------- K4: loss + usage ---------------------------------------------
__global__ void k4_final(float* __restrict__ out, int T) {
    int t = blockIdx.x * 256 + threadIdx.x;
    if (t < K_CB) out[1 + (size_t)T * D_IN + t] = (float)g_hist[t] * (1.0f / (float)T);
    if (blockIdx.x == 0) {
        double s = 0.0;
        for (int i = threadIdx.x; i < 8192; i += 256) s += g_partial[i];
        __shared__ double sh[256];
        sh[threadIdx.x] = s;
        __syncthreads();
        for (int d = 128; d >= 1; d >>= 1) {
            if (threadIdx.x < d) sh[threadIdx.x] += sh[threadIdx.x + d];
            __syncthreads();
        }
        if (threadIdx.x == 0)
            out[0] = (float)(1.25 * sh[0] / ((double)T * (double)D_IN));
    }
}

// ---------------- launch --------------------------------------------------------
extern "C" void kernel_launch(void* const* d_in, const int* in_sizes, int n_in,
                              void* d_out, int out_size) {
    const float* inputs    = (const float*)d_in[0];
    const float* bn1_gamma = (const float*)d_in[1];
    const float* bn1_beta  = (const float*)d_in[2];
    const float* W1        = (const float*)d_in[3];
    const float* b1        = (const float*)d_in[4];
    const float* emb       = (const float*)d_in[5];
    const float* bn2_gamma = (const float*)d_in[6];
    const float* bn2_beta  = (const float*)d_in[7];
    const float* W2        = (const float*)d_in[8];
    const float* b2        = (const float*)d_in[9];
    float* out = (float*)d_out;
    const int T = in_sizes[0] / D_IN;   // 65536

    float af = (float)(1.0 + 1e-5);
    float S = 1.0f / sqrtf(af);

    float* w1t; cudaGetSymbolAddress((void**)&w1t, g_W1T);
    float* w2t; cudaGetSymbolAddress((void**)&w2t, g_W2T);

    {
        dim3 blk(32, 8);
        kT_transpose<<<dim3(D_IN / 32, D_EMB / 32), blk>>>(W1, w1t, D_EMB, D_IN);
        kT_transpose<<<dim3(D_EMB / 32, D_IN / 32), blk>>>(W2, w2t, D_IN, D_EMB);
    }
    k0_init<<<8, 256>>>(b1, bn1_beta);
    k1_precompute<<<K_CB / K1_ROWS, 256>>>(emb, W1, bn1_gamma, bn2_gamma, bn2_beta, b2);
    k1b_c<<<K_CB / 8, 256>>>(emb);
    cudaFuncSetAttribute(k2_wmma, cudaFuncAttributeMaxDynamicSharedMemorySize, K2W_SMEM);
    k2_wmma<<<T / MT, 256, K2W_SMEM>>>(inputs);
    k_exact<<<NB_EXACT, 256>>>(inputs, bn1_gamma, bn1_beta, b1, emb, S);
    k3_gather<<<8192, 256>>>(inputs, out + 1);
    k4_final<<<8, 256>>>(out, T);
}

// round 10
// speedup vs baseline: 1.6227x; 1.0240x over previous
#include <cuda_runtime.h>
#include <cuda_bf16.h>
#include <mma.h>
#include <math.h>
#include <stdint.h>

using namespace nvcuda;

#define D_IN   256
#define D_EMB  512
#define K_CB   2048
#define T_MAX  65536
#define MARGIN 1.4e-4f
#define NB_EXACT 2048

#define MT   128                 // tokens per CTA
#define FLD  264                 // bf16 pitch for token/A tiles
#define OLD  132                 // float pitch for output scan buffer
#define SZ_F (MT * FLD * 2)      // 67584 bytes
#define OFF_FLO (SZ_F)
#define OFF_A   (2 * SZ_F)
#define OFF_C   (3 * SZ_F)
#define K2W_SMEM (3 * SZ_F + K_CB * 4)   // 210944

// ---------------- scratch (device globals; no allocations allowed) -----------
__device__ __align__(16) float g_Q[K_CB * D_IN];
__device__ __align__(16) float g_W1T[D_IN * D_EMB];
__device__ __align__(16) float g_W2T[D_EMB * D_IN];
__device__ __align__(16) __nv_bfloat16 g_Ahi[K_CB * D_IN];  // [cb][i] row-major
__device__ __align__(16) __nv_bfloat16 g_Alo[K_CB * D_IN];
__device__ float g_c[K_CB];
__device__ float g_se[K_CB];
__device__ float g_b1eff[D_EMB];
__device__ int g_idx[T_MAX];
__device__ unsigned int g_hist[K_CB];
__device__ double g_partial[8192];
__device__ int g_ccount[T_MAX];
__device__ unsigned short g_cand[T_MAX][16];
__device__ int g_needy[T_MAX];
__device__ int g_nneedy;

static __device__ __forceinline__ uint32_t smem_u32(const void* p) {
    uint32_t a;
    asm("{ .reg .u64 t; cvta.to.shared.u64 t, %1; cvt.u32.u64 %0, t; }" : "=r"(a) : "l"(p));
    return a;
}
#define CP_COMMIT() asm volatile("cp.async.commit_group;" ::: "memory")
#define CP_WAIT(n)  asm volatile("cp.async.wait_group %0;" :: "n"(n) : "memory")

// ---------------- KT: tiled transpose ----------------------------------------
__global__ void kT_transpose(const float* __restrict__ src, float* __restrict__ dst,
                             int R, int C) {
    __shared__ float tile[32][33];
    int bx = blockIdx.x * 32, by = blockIdx.y * 32;
    int x = bx + threadIdx.x;
    int y = by + threadIdx.y;
#pragma unroll
    for (int j = 0; j < 32; j += 8)
        if (y + j < R && x < C) tile[threadIdx.y + j][threadIdx.x] = src[(size_t)(y + j) * C + x];
    __syncthreads();
    x = by + threadIdx.x;
    y = bx + threadIdx.y;
#pragma unroll
    for (int j = 0; j < 32; j += 8)
        if (y + j < C && x < R) dst[(size_t)(y + j) * R + x] = tile[threadIdx.x][threadIdx.y + j];
}

// ---------------- K0 -----------------------------------------------------------
__global__ void k0_init(const float* __restrict__ b1, const float* __restrict__ beta1) {
    int t = blockIdx.x * blockDim.x + threadIdx.x;
    if (t < D_EMB) {
        float s = b1[t];
        for (int i = 0; i < D_IN; i++) s = fmaf(beta1[i], g_W1T[(size_t)i * D_EMB + t], s);
        g_b1eff[t] = s;
    }
    if (t < K_CB) g_hist[t] = 0u;
    if (t == 0) g_nneedy = 0;
}

// ---------------- K1: precompute A (bf16 hi/lo split) and Q --------------------
#define K1_ROWS 8
#define EPAD 12
__global__ __launch_bounds__(256) void k1_precompute(
    const float* __restrict__ emb, const float* __restrict__ W1,
    const float* __restrict__ g1v, const float* __restrict__ g2v,
    const float* __restrict__ beta2, const float* __restrict__ b2) {
    __shared__ float sE[D_EMB * EPAD];
    __shared__ float sG2[D_EMB];
    __shared__ float sB2[D_EMB];
    const int t = threadIdx.x;
    const int k0 = blockIdx.x * K1_ROWS;
    const float bn_s = rsqrtf(1.0f + 1e-5f);

    {
        int r = t & 7, ov = t >> 3;   // 32 float4 lanes per row
        for (int pass = 0; pass < 4; pass++) {
            int o4 = ov + pass * 32;  // 0..127
            float4 v = *(const float4*)&emb[(size_t)(k0 + r) * D_EMB + o4 * 4];
            sE[(o4 * 4 + 0) * EPAD + r] = v.x;
            sE[(o4 * 4 + 1) * EPAD + r] = v.y;
            sE[(o4 * 4 + 2) * EPAD + r] = v.z;
            sE[(o4 * 4 + 3) * EPAD + r] = v.w;
        }
    }
    for (int i = t; i < D_EMB; i += 256) {
        sG2[i] = g2v[i] * bn_s;
        sB2[i] = beta2[i];
    }
    __syncthreads();

    const int j = t;
    float accA[K1_ROWS], accQ[K1_ROWS];
    float qc = 0.f;
#pragma unroll
    for (int r = 0; r < K1_ROWS; r++) { accA[r] = 0.f; accQ[r] = 0.f; }

#pragma unroll 4
    for (int o = 0; o < D_EMB; o++) {
        float w1 = W1[(size_t)o * D_IN + j];
        float w2 = g_W2T[(size_t)o * D_IN + j];
        float gw = sG2[o] * w2;
        qc = fmaf(sB2[o], w2, qc);
        const float* e = &sE[o * EPAD];
        float4 e0 = *(const float4*)(e + 0);
        float4 e1 = *(const float4*)(e + 4);
        float ev[8] = {e0.x, e0.y, e0.z, e0.w, e1.x, e1.y, e1.z, e1.w};
#pragma unroll
        for (int r = 0; r < K1_ROWS; r++) {
            accA[r] = fmaf(ev[r], w1, accA[r]);
            accQ[r] = fmaf(ev[r], gw, accQ[r]);
        }
    }
    float g1j = g1v[j] * bn_s;
    float b2j = b2[j];
#pragma unroll
    for (int r = 0; r < K1_ROWS; r++) {
        float a = g1j * accA[r];
        __nv_bfloat16 hi = __float2bfloat16(a);
        __nv_bfloat16 lo = __float2bfloat16(a - __bfloat162float(hi));
        g_Ahi[(size_t)(k0 + r) * D_IN + j] = hi;
        g_Alo[(size_t)(k0 + r) * D_IN + j] = lo;
        g_Q[(size_t)(k0 + r) * D_IN + j] = accQ[r] + qc + b2j;
    }
}

// ---------------- K1b: c[k] and se[k] ------------------------------------------
__global__ __launch_bounds__(256) void k1b_c(const float* __restrict__ emb) {
    int w = blockIdx.x * 8 + (threadIdx.x >> 5);
    int lane = threadIdx.x & 31;
    if (w >= K_CB) return;
    float s = 0.f, se = 0.f;
    for (int o = lane; o < D_EMB; o += 32) {
        float ev = emb[(size_t)w * D_EMB + o];
        s = fmaf(ev, g_b1eff[o] - 0.5f * ev, s);
        se = __fadd_rn(se, __fmul_rn(ev, ev));
    }
#pragma unroll
    for (int d = 16; d >= 1; d >>= 1) {
        s += __shfl_xor_sync(0xffffffffu, s, d);
        se = __fadd_rn(se, __shfl_xor_sync(0xffffffffu, se, d));
    }
    if (lane == 0) { g_c[w] = s; g_se[w] = se; }
}

// ---------------- K2: wmma bf16 3-split GEMM, cp.async chunk pipeline ----------
__global__ __launch_bounds__(256, 1) void k2_wmma(const float* __restrict__ inputs) {
    extern __shared__ __align__(16) char smem[];
    __nv_bfloat16* sFhi = (__nv_bfloat16*)smem;
    __nv_bfloat16* sFlo = (__nv_bfloat16*)(smem + OFF_FLO);
    __nv_bfloat16* sA   = (__nv_bfloat16*)(smem + OFF_A);
    float* sOut = (float*)(smem + OFF_A);          // reuses A buffer
    float* sC   = (float*)(smem + OFF_C);
    const int tid = threadIdx.x;
    const int wid = tid >> 5;
    const int t0 = blockIdx.x * MT;
    const int tok0 = (wid & 3) * 32;
    const int cb0l = (wid >> 2) * 64;
    const uint32_t sAu = smem_u32(sA);

    for (int i = tid; i < K_CB; i += 256) sC[i] = g_c[i];

    // stage tokens (bf16 hi/lo split, row-major [tok][FLD])
    for (int idx = tid; idx < MT * 64; idx += 256) {
        int tok = idx >> 6, q = idx & 63;
        float4 v = *(const float4*)&inputs[(size_t)(t0 + tok) * D_IN + q * 4];
        float f[4] = {v.x, v.y, v.z, v.w};
        uint32_t hp[2], lp[2];
#pragma unroll
        for (int pr = 0; pr < 2; pr++) {
            __nv_bfloat16 h0 = __float2bfloat16(f[pr * 2 + 0]);
            __nv_bfloat16 h1 = __float2bfloat16(f[pr * 2 + 1]);
            __nv_bfloat16 l0 = __float2bfloat16(f[pr * 2 + 0] - __bfloat162float(h0));
            __nv_bfloat16 l1 = __float2bfloat16(f[pr * 2 + 1] - __bfloat162float(h1));
            hp[pr] = (uint32_t)__bfloat16_as_ushort(h0) | ((uint32_t)__bfloat16_as_ushort(h1) << 16);
            lp[pr] = (uint32_t)__bfloat16_as_ushort(l0) | ((uint32_t)__bfloat16_as_ushort(l1) << 16);
        }
        *(uint2*)(sFhi + tok * FLD + q * 4) = make_uint2(hp[0], hp[1]);
        *(uint2*)(sFlo + tok * FLD + q * 4) = make_uint2(lp[0], lp[1]);
    }

    float v0 = -INFINITY, v1 = -INFINITY, v2 = -INFINITY;
    int i0 = 0, i1 = 0, i2 = 0;

    wmma::fragment<wmma::accumulator, 16, 16, 16, float> acc[2][4];

    // chunk = K-half (128 k = bytes [chunk*256, chunk*256+256) of each 528B row)
    auto copy_chunk = [&](const __nv_bfloat16* gbase, int chunk) {
        const char* src = (const char*)gbase;
#pragma unroll
        for (int z = 0; z < 8; z++) {
            int idx = tid + z * 256;            // 0..2047
            int r = idx >> 4, u = idx & 15;
            uint32_t d = sAu + (uint32_t)(r * (FLD * 2) + chunk * 256 + u * 16);
            const char* s = src + r * 512 + chunk * 256 + u * 16;
            asm volatile("cp.async.cg.shared.global [%0], [%1], 16;" :: "r"(d), "l"(s));
        }
    };
    auto mma_hi = [&](int chunk) {
#pragma unroll
        for (int ks = 0; ks < 8; ks++) {
            int k0 = (chunk * 8 + ks) * 16;
            wmma::fragment<wmma::matrix_a, 16, 16, 16, __nv_bfloat16, wmma::row_major> ah[2], al[2];
            wmma::fragment<wmma::matrix_b, 16, 16, 16, __nv_bfloat16, wmma::col_major> b[4];
#pragma unroll
            for (int mi = 0; mi < 2; mi++) {
                wmma::load_matrix_sync(ah[mi], sFhi + (tok0 + mi * 16) * FLD + k0, FLD);
                wmma::load_matrix_sync(al[mi], sFlo + (tok0 + mi * 16) * FLD + k0, FLD);
            }
#pragma unroll
            for (int ni = 0; ni < 4; ni++)
                wmma::load_matrix_sync(b[ni], sA + (cb0l + ni * 16) * FLD + k0, FLD);
#pragma unroll
            for (int ni = 0; ni < 4; ni++)
#pragma unroll
                for (int mi = 0; mi < 2; mi++) {
                    wmma::mma_sync(acc[mi][ni], ah[mi], b[ni], acc[mi][ni]);
                    wmma::mma_sync(acc[mi][ni], al[mi], b[ni], acc[mi][ni]);
                }
        }
    };
    auto mma_lo = [&](int chunk) {
#pragma unroll
        for (int ks = 0; ks < 8; ks++) {
            int k0 = (chunk * 8 + ks) * 16;
            wmma::fragment<wmma::matrix_a, 16, 16, 16, __nv_bfloat16, wmma::row_major> ah[2];
            wmma::fragment<wmma::matrix_b, 16, 16, 16, __nv_bfloat16, wmma::col_major> b[4];
#pragma unroll
            for (int mi = 0; mi < 2; mi++)
                wmma::load_matrix_sync(ah[mi], sFhi + (tok0 + mi * 16) * FLD + k0, FLD);
#pragma unroll
            for (int ni = 0; ni < 4; ni++)
                wmma::load_matrix_sync(b[ni], sA + (cb0l + ni * 16) * FLD + k0, FLD);
#pragma unroll
            for (int ni = 0; ni < 4; ni++)
#pragma unroll
                for (int mi = 0; mi < 2; mi++)
                    wmma::mma_sync(acc[mi][ni], ah[mi], b[ni], acc[mi][ni]);
        }
    };

    for (int ct = 0; ct < 16; ct++) {
        __syncthreads();                 // prev scan done (or token staging), sA free
        const __nv_bfloat16* baseHi = g_Ahi + (size_t)ct * 128 * D_IN;
        const __nv_bfloat16* baseLo = g_Alo + (size_t)ct * 128 * D_IN;
        copy_chunk(baseHi, 0); CP_COMMIT();      // g1
        copy_chunk(baseHi, 1); CP_COMMIT();      // g2
#pragma unroll
        for (int mi = 0; mi < 2; mi++)
#pragma unroll
            for (int ni = 0; ni < 4; ni++) wmma::fill_fragment(acc[mi][ni], 0.0f);
        CP_WAIT(1); __syncthreads();             // H0 ready
        mma_hi(0);
        __syncthreads();                          // chunk0 readers done
        copy_chunk(baseLo, 0); CP_COMMIT();      // g3 (overlaps mma_hi(1))
        CP_WAIT(1); __syncthreads();             // H1 ready
        mma_hi(1);
        __syncthreads();                          // chunk1 readers done
        copy_chunk(baseLo, 1); CP_COMMIT();      // g4 (overlaps mma_lo(0))
        CP_WAIT(1); __syncthreads();             // L0 ready
        mma_lo(0);
        CP_WAIT(0); __syncthreads();             // L1 ready
        mma_lo(1);
        __syncthreads();                          // all mma done; sA -> sOut
#pragma unroll
        for (int mi = 0; mi < 2; mi++)
#pragma unroll
            for (int ni = 0; ni < 4; ni++)
                wmma::store_matrix_sync(sOut + (tok0 + mi * 16) * OLD + cb0l + ni * 16,
                                        acc[mi][ni], OLD, wmma::mem_row_major);
        __syncthreads();
        {   // scan: 2 threads per token, 64 cb each, ascending index
            int tok = tid >> 1, half = tid & 1;
            const float* row = sOut + tok * OLD + half * 64;
            const float* cc = sC + ct * 128 + half * 64;
            int cbb = ct * 128 + half * 64;
#pragma unroll 4
            for (int j = 0; j < 64; j++) {
                float s = row[j] + cc[j];
                if (s > v2) {
                    int cb = cbb + j;
                    if (s > v1) {
                        if (s > v0) { v2 = v1; i2 = i1; v1 = v0; i1 = i0; v0 = s; i0 = cb; }
                        else        { v2 = v1; i2 = i1; v1 = s; i1 = cb; }
                    } else          { v2 = s; i2 = cb; }
                }
            }
        }
    }

    // merge the two half-scans of each token (value desc, index asc)
    {
        float pv[3];
        int pi[3];
        pv[0] = __shfl_xor_sync(0xffffffffu, v0, 1); pi[0] = __shfl_xor_sync(0xffffffffu, i0, 1);
        pv[1] = __shfl_xor_sync(0xffffffffu, v1, 1); pi[1] = __shfl_xor_sync(0xffffffffu, i1, 1);
        pv[2] = __shfl_xor_sync(0xffffffffu, v2, 1); pi[2] = __shfl_xor_sync(0xffffffffu, i2, 1);
#pragma unroll
        for (int e = 0; e < 3; e++) {
            float s = pv[e]; int cb = pi[e];
            bool b0 = s > v0 || (s == v0 && cb < i0);
            bool b1 = s > v1 || (s == v1 && cb < i1);
            bool b2 = s > v2 || (s == v2 && cb < i2);
            if (b0) { v2 = v1; i2 = i1; v1 = v0; i1 = i0; v0 = s; i0 = cb; }
            else if (b1) { v2 = v1; i2 = i1; v1 = s; i1 = cb; }
            else if (b2) { v2 = s; i2 = cb; }
        }
    }
    if ((tid & 1) == 0) {
        int tok = t0 + (tid >> 1);
        float thr = v0 - MARGIN;
        if (v2 >= thr) {
            g_ccount[tok] = 17;
            int p = atomicAdd(&g_nneedy, 1);
            g_needy[p] = tok;
        } else if (v1 >= thr) {
            g_ccount[tok] = 2;
            g_cand[tok][0] = (unsigned short)i0;
            g_cand[tok][1] = (unsigned short)i1;
            int p = atomicAdd(&g_nneedy, 1);
            g_needy[p] = tok;
        } else {
            g_ccount[tok] = 1;
            g_idx[tok] = i0;
            atomicAdd(&g_hist[i0], 1u);
        }
    }
}

// ---------------- K_exact: jax-emulated fp32 distances, 4-token batches --------
// Per-token FMA chains identical to the verified version (bitwise).
__global__ __launch_bounds__(256) void k_exact(
    const float* __restrict__ inputs, const float* __restrict__ g1v,
    const float* __restrict__ beta1, const float* __restrict__ b1,
    const float* __restrict__ emb, float S) {
    __shared__ float sXin[4][D_IN];
    __shared__ float sX[4][D_EMB];
    __shared__ float sRed[256];
    __shared__ int sRedI[256];
    __shared__ float sSx[4];
    __shared__ int sTok[4];
    const int tid = threadIdx.x;
    const int n = g_nneedy;
    for (int base = blockIdx.x * 4; base < n; base += gridDim.x * 4) {
        int nb = n - base; if (nb > 4) nb = 4;
        if (tid < 4) sTok[tid] = g_needy[base + (tid < nb ? tid : 0)];
        __syncthreads();
        {
            float sc = __fmul_rn(g1v[tid], S);
            float bt = beta1[tid];
#pragma unroll
            for (int j = 0; j < 4; j++) {
                float f = inputs[(size_t)sTok[j] * D_IN + tid];
                sXin[j][tid] = __fadd_rn(__fmul_rn(f, sc), bt);
            }
        }
        __syncthreads();
        if (tid < 128) {
            int ob = tid * 4;
            float a[4][4];
#pragma unroll
            for (int j = 0; j < 4; j++)
#pragma unroll
                for (int c = 0; c < 4; c++) a[j][c] = 0.f;
#pragma unroll 4
            for (int i = 0; i < D_IN; i++) {
                float4 w = *(const float4*)(g_W1T + (size_t)i * D_EMB + ob);
#pragma unroll
                for (int j = 0; j < 4; j++) {
                    float xi = sXin[j][i];
                    a[j][0] = fmaf(xi, w.x, a[j][0]);
                    a[j][1] = fmaf(xi, w.y, a[j][1]);
                    a[j][2] = fmaf(xi, w.z, a[j][2]);
                    a[j][3] = fmaf(xi, w.w, a[j][3]);
                }
            }
#pragma unroll
            for (int j = 0; j < 4; j++) {
                sX[j][ob + 0] = __fadd_rn(a[j][0], b1[ob + 0]);
                sX[j][ob + 1] = __fadd_rn(a[j][1], b1[ob + 1]);
                sX[j][ob + 2] = __fadd_rn(a[j][2], b1[ob + 2]);
                sX[j][ob + 3] = __fadd_rn(a[j][3], b1[ob + 3]);
            }
        }
        __syncthreads();
        {   // sx per token (same reduction order as verified version)
            float p[4];
#pragma unroll
            for (int j = 0; j < 4; j++)
                p[j] = __fadd_rn(__fmul_rn(sX[j][tid], sX[j][tid]),
                                 __fmul_rn(sX[j][tid + 256], sX[j][tid + 256]));
#pragma unroll
            for (int d = 16; d >= 1; d >>= 1)
#pragma unroll
                for (int j = 0; j < 4; j++)
                    p[j] = __fadd_rn(p[j], __shfl_xor_sync(0xffffffffu, p[j], d));
            if ((tid & 31) == 0)
#pragma unroll
                for (int j = 0; j < 4; j++) sRed[j * 8 + (tid >> 5)] = p[j];
            __syncthreads();
            if (tid < 4) {
                float s = 0.f;
#pragma unroll
                for (int w = 0; w < 8; w++) s = __fadd_rn(s, sRed[tid * 8 + w]);
                sSx[tid] = s;
            }
            __syncthreads();
        }
        for (int j = 0; j < nb; j++) {
            int t = sTok[j];
            float sx = sSx[j];
            int cnt = g_ccount[t];
            int C = (cnt <= 16) ? cnt : K_CB;
            float bd = INFINITY;
            int bk = 0x7fffffff;
            for (int ci = tid; ci < C; ci += 256) {
                int k = (cnt <= 16) ? (int)g_cand[t][ci] : ci;
                const float4* e4 = (const float4*)(emb + (size_t)k * D_EMB);
                float m = 0.f;
#pragma unroll 4
                for (int o4 = 0; o4 < D_EMB / 4; o4++) {
                    float4 e = e4[o4];
                    m = fmaf(sX[j][o4 * 4 + 0], e.x, m);
                    m = fmaf(sX[j][o4 * 4 + 1], e.y, m);
                    m = fmaf(sX[j][o4 * 4 + 2], e.z, m);
                    m = fmaf(sX[j][o4 * 4 + 3], e.w, m);
                }
                float d = __fsub_rn(__fadd_rn(sx, g_se[k]), __fmul_rn(2.0f, m));
                if (d < bd || (d == bd && k < bk)) { bd = d; bk = k; }
            }
            sRed[tid] = bd; sRedI[tid] = bk;
            __syncthreads();
            for (int d = 128; d >= 1; d >>= 1) {
                if (tid < d) {
                    float od = sRed[tid + d]; int ok = sRedI[tid + d];
                    if (od < sRed[tid] || (od == sRed[tid] && ok < sRedI[tid])) {
                        sRed[tid] = od; sRedI[tid] = ok;
                    }
                }
                __syncthreads();
            }
            if (tid == 0) { g_idx[t] = sRedI[0]; atomicAdd(&g_hist[sRedI[0]], 1u); }
            __syncthreads();
        }
    }
}

// ---------------- K3: gather + straight-through + SSE partials -----------------
__global__ __launch_bounds__(256) void k3_gather(const float* __restrict__ inputs,
                                                 float* __restrict__ outq) {
    const int t = threadIdx.x;
    float s = 0.f;
#pragma unroll
    for (int r = 0; r < 8; r++) {
        int gid = blockIdx.x * 2048 + r * 256 + t;
        int tok = gid >> 8;
        int j = gid & 255;
        int idx = g_idx[tok];
        float q = g_Q[(size_t)idx * D_IN + j];
        float x = inputs[gid];
        float d = __fsub_rn(q, x);
        outq[gid] = __fadd_rn(x, d);
        s = fmaf(d, d, s);
    }
#pragma unroll
    for (int d = 16; d >= 1; d >>= 1) s += __shfl_xor_sync(0xffffffffu, s, d);
    __shared__ float wsum[8];
    if ((t & 31) == 0) wsum[t >> 5] = s;
    __syncthreads();
    if (t == 0) {
        float tot = 0.f;
#pragma unroll
        for (int w = 0; w < 8; w++) tot += wsum[w];
        g_partial[blockIdx.x] = (double)tot;
    }
}

// ---------------- K4: loss + usage ---------------------------------------------
__global__ void k4_final(float* __restrict__ out, int T) {
    int t = blockIdx.x * 256 + threadIdx.x;
    if (t < K_CB) out[1 + (size_t)T * D_IN + t] = (float)g_hist[t] * (1.0f / (float)T);
    if (blockIdx.x == 0) {
        double s = 0.0;
        for (int i = threadIdx.x; i < 8192; i += 256) s += g_partial[i];
        __shared__ double sh[256];
        sh[threadIdx.x] = s;
        __syncthreads();
        for (int d = 128; d >= 1; d >>= 1) {
            if (threadIdx.x < d) sh[threadIdx.x] += sh[threadIdx.x + d];
            __syncthreads();
        }
        if (threadIdx.x == 0)
            out[0] = (float)(1.25 * sh[0] / ((double)T * (double)D_IN));
    }
}

// ---------------- launch --------------------------------------------------------
extern "C" void kernel_launch(void* const* d_in, const int* in_sizes, int n_in,
                              void* d_out, int out_size) {
    const float* inputs    = (const float*)d_in[0];
    const float* bn1_gamma = (const float*)d_in[1];
    const float* bn1_beta  = (const float*)d_in[2];
    const float* W1        = (const float*)d_in[3];
    const float* b1        = (const float*)d_in[4];
    const float* emb       = (const float*)d_in[5];
    const float* bn2_gamma = (const float*)d_in[6];
    const float* bn2_beta  = (const float*)d_in[7];
    const float* W2        = (const float*)d_in[8];
    const float* b2        = (const float*)d_in[9];
    float* out = (float*)d_out;
    const int T = in_sizes[0] / D_IN;   // 65536

    float af = (float)(1.0 + 1e-5);
    float S = 1.0f / sqrtf(af);

    float* w1t; cudaGetSymbolAddress((void**)&w1t, g_W1T);
    float* w2t; cudaGetSymbolAddress((void**)&w2t, g_W2T);

    {
        dim3 blk(32, 8);
        kT_transpose<<<dim3(D_IN / 32, D_EMB / 32), blk>>>(W1, w1t, D_EMB, D_IN);
        kT_transpose<<<dim3(D_EMB / 32, D_IN / 32), blk>>>(W2, w2t, D_IN, D_EMB);
    }
    k0_init<<<8, 256>>>(b1, bn1_beta);
    k1_precompute<<<K_CB / K1_ROWS, 256>>>(emb, W1, bn1_gamma, bn2_gamma, bn2_beta, b2);
    k1b_c<<<K_CB / 8, 256>>>(emb);
    cudaFuncSetAttribute(k2_wmma, cudaFuncAttributeMaxDynamicSharedMemorySize, K2W_SMEM);
    k2_wmma<<<T / MT, 256, K2W_SMEM>>>(inputs);
    k_exact<<<NB_EXACT, 256>>>(inputs, bn1_gamma, bn1_beta, b1, emb, S);
    k3_gather<<<8192, 256>>>(inputs, out + 1);
    k4_final<<<8, 256>>>(out, T);
}